// round 13
// baseline (speedup 1.0000x reference)
#include <cuda_runtime.h>
#include <cuda_fp16.h>
#include <math.h>

#define NN 100000
#define NE 1600000
#define IND 128
#define HID 64
#define NC 40
#define CAP 64              // bucket slots per row (P(deg>=64) ~ 1e-20)

// Scratch (allocation-free per harness rules)
__device__ __half g_hA[(size_t)NN * HID];    // half intermediates (12.8 MB each)
__device__ __half g_hB[(size_t)NN * HID];
__device__ int    g_cnt[NN];
__device__ int4   g_epack4[(size_t)NN * (CAP / 2)];  // 64 slots x 8B per row, 512B-aligned rows

// ---------------------------------------------------------------------------
// Bucket scatter: one atomic + one 8B store per edge. No hist/scan needed.
// ---------------------------------------------------------------------------
__global__ __launch_bounds__(256) void scatter_kernel(
    const int4* __restrict__ er4, const int4* __restrict__ ec4,
    const float4* __restrict__ ev4) {
    int i = blockIdx.x * 256 + threadIdx.x;
    if (i >= NE / 4) return;
    int4 r = __ldg(er4 + i);
    int4 c = __ldg(ec4 + i);
    float4 v = __ldg(ev4 + i);
    int2* ep = (int2*)g_epack4;
    int p0 = atomicAdd(&g_cnt[r.x], 1);
    int p1 = atomicAdd(&g_cnt[r.y], 1);
    int p2 = atomicAdd(&g_cnt[r.z], 1);
    int p3 = atomicAdd(&g_cnt[r.w], 1);
    ep[((size_t)r.x << 6) + p0] = make_int2(c.x, __float_as_int(v.x));
    ep[((size_t)r.y << 6) + p1] = make_int2(c.y, __float_as_int(v.y));
    ep[((size_t)r.z << 6) + p2] = make_int2(c.z, __float_as_int(v.z));
    ep[((size_t)r.w << 6) + p3] = make_int2(c.w, __float_as_int(v.w));
}

// ---------------------------------------------------------------------------
// GEMM: C[NN,64](half) = act(A)[NN,K] @ W[K,64] + bias
// ---------------------------------------------------------------------------
template <int K, bool RELU, bool HIN>
__global__ __launch_bounds__(256) void gemm128_kernel(
    const void* __restrict__ Av, const float* __restrict__ W,
    const float* __restrict__ bias, __half* __restrict__ C) {
    __shared__ float As[128][36];
    __shared__ float Ws[32][64];

    const int t  = threadIdx.x;
    const int tx = t & 15;
    const int ty = t >> 4;
    const int row0 = blockIdx.x * 128;

    float acc[8][4];
#pragma unroll
    for (int i = 0; i < 8; i++)
#pragma unroll
        for (int j = 0; j < 4; j++) acc[i][j] = 0.f;

    for (int kt = 0; kt < K; kt += 32) {
#pragma unroll
        for (int u = 0; u < 4; u++) {
            int f = t + u * 256;
            int r = f >> 3;
            int kc = (f & 7) << 2;
            int grow = row0 + r;
            float4 v = make_float4(0.f, 0.f, 0.f, 0.f);
            if (grow < NN) {
                if (HIN) {
                    const __half* A = (const __half*)Av;
                    uint2 raw = __ldg(reinterpret_cast<const uint2*>(
                        A + (size_t)grow * K + kt + kc));
                    float2 f0 = __half22float2(*reinterpret_cast<__half2*>(&raw.x));
                    float2 f1 = __half22float2(*reinterpret_cast<__half2*>(&raw.y));
                    v = make_float4(f0.x, f0.y, f1.x, f1.y);
                } else {
                    const float* A = (const float*)Av;
                    v = *reinterpret_cast<const float4*>(A + (size_t)grow * K + kt + kc);
                }
            }
            if (RELU) {
                v.x = fmaxf(v.x, 0.f); v.y = fmaxf(v.y, 0.f);
                v.z = fmaxf(v.z, 0.f); v.w = fmaxf(v.w, 0.f);
            }
            *reinterpret_cast<float4*>(&As[r][kc]) = v;
        }
#pragma unroll
        for (int u = 0; u < 2; u++) {
            int f = t + u * 256;
            int r = f >> 4;
            int c = (f & 15) << 2;
            *reinterpret_cast<float4*>(&Ws[r][c]) =
                *reinterpret_cast<const float4*>(W + (size_t)(kt + r) * 64 + c);
        }
        __syncthreads();

#pragma unroll
        for (int kk = 0; kk < 32; kk += 4) {
            float4 a[8];
#pragma unroll
            for (int i = 0; i < 8; i++)
                a[i] = *reinterpret_cast<const float4*>(&As[(ty << 3) + i][kk]);
#pragma unroll
            for (int j = 0; j < 4; j++) {
                float4 b = *reinterpret_cast<const float4*>(&Ws[kk + j][tx << 2]);
#pragma unroll
                for (int i = 0; i < 8; i++) {
                    float s = (j == 0) ? a[i].x : (j == 1) ? a[i].y
                            : (j == 2) ? a[i].z : a[i].w;
                    acc[i][0] += s * b.x; acc[i][1] += s * b.y;
                    acc[i][2] += s * b.z; acc[i][3] += s * b.w;
                }
            }
        }
        __syncthreads();
    }

    float4 bv = *reinterpret_cast<const float4*>(bias + (tx << 2));
#pragma unroll
    for (int i = 0; i < 8; i++) {
        int grow = row0 + (ty << 3) + i;
        if (grow < NN) {
            __half2 o01 = __floats2half2_rn(acc[i][0] + bv.x, acc[i][1] + bv.y);
            __half2 o23 = __floats2half2_rn(acc[i][2] + bv.z, acc[i][3] + bv.w);
            uint2 st;
            st.x = *reinterpret_cast<unsigned*>(&o01);
            st.y = *reinterpret_cast<unsigned*>(&o23);
            *reinterpret_cast<uint2*>(C + (size_t)grow * 64 + (tx << 2)) = st;
        }
    }
}

// ---------------------------------------------------------------------------
// Bucket SpMM gather: 8 threads/row, 16B dense slices, int4 edge loads
// (512B-aligned row base -> no peel needed).
// ---------------------------------------------------------------------------
struct Acc8 { float4 lo, hi; };

__device__ __forceinline__ void acc_edge(Acc8& a, const __half* __restrict__ base,
                                         int c, float v) {
    uint4 r = __ldg(reinterpret_cast<const uint4*>(base + (size_t)c * HID));
    float2 f0 = __half22float2(*reinterpret_cast<__half2*>(&r.x));
    float2 f1 = __half22float2(*reinterpret_cast<__half2*>(&r.y));
    float2 f2 = __half22float2(*reinterpret_cast<__half2*>(&r.z));
    float2 f3 = __half22float2(*reinterpret_cast<__half2*>(&r.w));
    a.lo.x += v * f0.x; a.lo.y += v * f0.y;
    a.lo.z += v * f1.x; a.lo.w += v * f1.y;
    a.hi.x += v * f2.x; a.hi.y += v * f2.y;
    a.hi.z += v * f3.x; a.hi.w += v * f3.y;
}

__device__ __forceinline__ Acc8 row_acc8(const __half* __restrict__ dense,
                                         int row, int lane) {
    int cnt = __ldg(g_cnt + row);
    const __half* base = dense + lane * 8;
    const int4* ep4 = g_epack4 + ((size_t)row << 5);   // 32 int4 per row
    const int2* ep2 = (const int2*)ep4;
    Acc8 a;
    a.lo = make_float4(0.f, 0.f, 0.f, 0.f);
    a.hi = make_float4(0.f, 0.f, 0.f, 0.f);
    int i = 0;
    for (; i + 4 <= cnt; i += 4) {
        int4 p0 = __ldg(ep4 + (i >> 1));
        int4 p1 = __ldg(ep4 + (i >> 1) + 1);
        acc_edge(a, base, p0.x, __int_as_float(p0.y));
        acc_edge(a, base, p0.z, __int_as_float(p0.w));
        acc_edge(a, base, p1.x, __int_as_float(p1.y));
        acc_edge(a, base, p1.z, __int_as_float(p1.w));
    }
    for (; i < cnt; i++) {
        int2 e0 = __ldg(ep2 + i);
        acc_edge(a, base, e0.x, __int_as_float(e0.y));
    }
    return a;
}

__global__ __launch_bounds__(256) void spmm_kernel(
    const __half* __restrict__ dense, __half* __restrict__ out) {
    int row = blockIdx.x * 32 + (threadIdx.x >> 3);
    if (row >= NN) return;
    int lane = threadIdx.x & 7;
    Acc8 a = row_acc8(dense, row, lane);
    __half2 h0 = __floats2half2_rn(a.lo.x, a.lo.y);
    __half2 h1 = __floats2half2_rn(a.lo.z, a.lo.w);
    __half2 h2 = __floats2half2_rn(a.hi.x, a.hi.y);
    __half2 h3 = __floats2half2_rn(a.hi.z, a.hi.w);
    uint4 st;
    st.x = *reinterpret_cast<unsigned*>(&h0);
    st.y = *reinterpret_cast<unsigned*>(&h1);
    st.z = *reinterpret_cast<unsigned*>(&h2);
    st.w = *reinterpret_cast<unsigned*>(&h3);
    *reinterpret_cast<uint4*>(out + (size_t)row * HID + lane * 8) = st;
}

// ---------------------------------------------------------------------------
// Fused: h2 = spmm(dense) ; out = log_softmax(h2 @ Wc + bc)  (fp32 math)
// ---------------------------------------------------------------------------
__global__ __launch_bounds__(256) void spmm_cls_kernel(
    const __half* __restrict__ dense, const float* __restrict__ Wc,
    const float* __restrict__ bc, float* __restrict__ out) {
    __shared__ float hs[32][72];
    __shared__ float Wcs[HID * NC];
    __shared__ float bcs[NC];

    const int t = threadIdx.x;
    for (int i = t; i < HID * NC; i += 256) Wcs[i] = Wc[i];
    if (t < NC) bcs[t] = bc[t];

    const int lrow = t >> 3;
    const int row = blockIdx.x * 32 + lrow;
    const int lane = t & 7;

    Acc8 a;
    a.lo = make_float4(0.f, 0.f, 0.f, 0.f);
    a.hi = make_float4(0.f, 0.f, 0.f, 0.f);
    if (row < NN) a = row_acc8(dense, row, lane);
    *reinterpret_cast<float4*>(&hs[lrow][lane * 8])     = a.lo;
    *reinterpret_cast<float4*>(&hs[lrow][lane * 8 + 4]) = a.hi;
    __syncthreads();

    const int w = t >> 5, lane32 = t & 31;
    const int j2 = lane32 + 32;
    const int j2c = (j2 < NC) ? j2 : 0;

    for (int rr = w; rr < 32; rr += 8) {
        int node = blockIdx.x * 32 + rr;
        if (node >= NN) continue;

        float l1 = bcs[lane32];
        float l2 = bcs[j2c];
#pragma unroll 8
        for (int k = 0; k < HID; k++) {
            float h = hs[rr][k];
            l1 += h * Wcs[k * NC + lane32];
            l2 += h * Wcs[k * NC + j2c];
        }
        if (j2 >= NC) l2 = -INFINITY;

        float m = fmaxf(l1, l2);
#pragma unroll
        for (int o = 16; o; o >>= 1) m = fmaxf(m, __shfl_xor_sync(0xffffffffu, m, o));
        float s = expf(l1 - m) + ((j2 < NC) ? expf(l2 - m) : 0.f);
#pragma unroll
        for (int o = 16; o; o >>= 1) s += __shfl_xor_sync(0xffffffffu, s, o);
        float lse = m + logf(s);

        out[(size_t)node * NC + lane32] = l1 - lse;
        if (j2 < NC) out[(size_t)node * NC + j2] = l2 - lse;
    }
}

// ---------------------------------------------------------------------------
extern "C" void kernel_launch(void* const* d_in, const int* in_sizes, int n_in,
                              void* d_out, int out_size) {
    const float* x  = (const float*)d_in[0];
    const int*   er = (const int*)d_in[1];
    const int*   ec = (const int*)d_in[2];
    const float* ev = (const float*)d_in[3];
    const float* W1 = (const float*)d_in[4];
    const float* b1 = (const float*)d_in[5];
    const float* W2 = (const float*)d_in[6];
    const float* b2 = (const float*)d_in[7];
    const float* Wc = (const float*)d_in[8];
    const float* bc = (const float*)d_in[9];
    float* out = (float*)d_out;

    __half *hA, *hB;
    cudaGetSymbolAddress((void**)&hA, g_hA);
    cudaGetSymbolAddress((void**)&hB, g_hB);
    int* cntp;
    cudaGetSymbolAddress((void**)&cntp, g_cnt);

    // One-time resource init (streams/events only; identical GPU work each call).
    static cudaStream_t sB = nullptr;
    static cudaEvent_t evFork = nullptr, evJoin = nullptr;
    if (sB == nullptr) {
        cudaStreamCreateWithFlags(&sB, cudaStreamNonBlocking);
        cudaEventCreateWithFlags(&evFork, cudaEventDisableTiming);
        cudaEventCreateWithFlags(&evJoin, cudaEventDisableTiming);
    }

    const int edge4_grid = (NE / 4 + 255) / 256;         // 1563
    const int gemm_grid  = (NN + 127) / 128;             // 782
    const int spmm_grid  = (NN + 31) / 32;               // 3125

    // --- Fork: bucket build on side stream, gemm1 on capture stream ---
    cudaEventRecord(evFork, 0);
    cudaStreamWaitEvent(sB, evFork, 0);

    cudaMemsetAsync(cntp, 0, (size_t)NN * sizeof(int), sB);
    scatter_kernel<<<edge4_grid, 256, 0, sB>>>((const int4*)er, (const int4*)ec,
                                               (const float4*)ev);
    cudaEventRecord(evJoin, sB);

    // Layer 1 GEMM overlaps the build: support1 = x@W1+b1 (half out)
    gemm128_kernel<IND, false, false><<<gemm_grid, 256>>>(x, W1, b1, hA);

    // --- Join: spmm1 needs both buckets and support1 ---
    cudaStreamWaitEvent(0, evJoin, 0);
    spmm_kernel<<<spmm_grid, 256>>>(hA, hB);

    // --- Layer 2: support2 = relu(h1)@W2+b2 ; out = cls(spmm(support2)) ---
    gemm128_kernel<HID, true, true><<<gemm_grid, 256>>>(hB, W2, b2, hA);
    spmm_cls_kernel<<<spmm_grid, 256>>>(hA, Wc, bc, out);
}